// round 2
// baseline (speedup 1.0000x reference)
#include <cuda_runtime.h>
#include <cuda_fp16.h>

#define Ln   6368
#define Tt   128
#define Bb   4
#define H1n  2133
#define H2n  4250
#define CHUNK 2048

// ---------------- device state (static allocations, allowed) ----------------
__device__ __align__(16) __half g_E[(size_t)Ln * Ln];       // packed (A - 0.999 I) fp16, 81 MB
__device__ __align__(16) float  g_theta[2][Ln * Bb];        // ping-pong theta, [j][b] layout
__device__ __align__(16) float  g_h1[H1n * Bb];
__device__ __align__(16) float  g_h2[H2n * Bb];
__device__ __align__(16) float  g_xhat[Tt][Bb][16];         // tanh(mean) outputs per step

// ---------------- f32x2 helpers ----------------
__device__ __forceinline__ unsigned long long pk2(float lo, float hi) {
    unsigned long long r;
    asm("mov.b64 %0, {%1,%2};" : "=l"(r) : "f"(lo), "f"(hi));
    return r;
}
__device__ __forceinline__ void upk2(unsigned long long v, float& lo, float& hi) {
    asm("mov.b64 {%0,%1}, %2;" : "=f"(lo), "=f"(hi) : "l"(v));
}
__device__ __forceinline__ void fma2(unsigned long long& d, unsigned long long a, unsigned long long b) {
    asm("fma.rn.f32x2 %0, %1, %2, %0;" : "+l"(d) : "l"(a), "l"(b));
}
__device__ __forceinline__ unsigned long long add2(unsigned long long a, unsigned long long b) {
    unsigned long long r;
    asm("add.rn.f32x2 %0, %1, %2;" : "=l"(r) : "l"(a), "l"(b));
    return r;
}
__device__ __forceinline__ unsigned long long h2ff(unsigned int h) {
    __half2 hh = *reinterpret_cast<__half2*>(&h);
    float2 f = __half22float2(hh);
    return pk2(f.x, f.y);
}

// ---------------- E conversion: Epack[(row/8)*L + j][row%8] = A[row][j] - 0.999*(row==j) ----------------
__global__ void cvt_E(const float* __restrict__ A) {
    size_t idx = (size_t)blockIdx.x * blockDim.x + threadIdx.x;
    const int J4 = Ln / 4;  // 1592
    if (idx >= (size_t)Ln * J4) return;
    int row = (int)(idx / J4);
    int j0  = (int)(idx % J4) * 4;
    float4 a = reinterpret_cast<const float4*>(A)[idx];
    float v0 = a.x, v1 = a.y, v2 = a.z, v3 = a.w;
    if (row == j0)     v0 -= 0.999f;
    if (row == j0 + 1) v1 -= 0.999f;
    if (row == j0 + 2) v2 -= 0.999f;
    if (row == j0 + 3) v3 -= 0.999f;
    int t = row >> 3, r = row & 7;
    size_t base = (((size_t)t * Ln + j0) << 3) + r;
    g_E[base]      = __float2half(v0);
    g_E[base + 8]  = __float2half(v1);
    g_E[base + 16] = __float2half(v2);
    g_E[base + 24] = __float2half(v3);
}

// ---------------- init MLP stage 1: h1 = relu(W1 @ xs[:,0] + b1) ----------------
__global__ void mlp1_kernel(const float* __restrict__ W1, const float* __restrict__ b1,
                            const float* __restrict__ xs) {
    int t = blockIdx.x * blockDim.x + threadIdx.x;
    if (t >= H1n * Bb) return;
    int row = t >> 2, b = t & 3;
    float a = b1[row];
    const float* x0 = xs + (size_t)b * Tt * 16;   // xs[b][0][:]
#pragma unroll
    for (int d = 0; d < 16; d++) a = fmaf(W1[row * 16 + d], x0[d], a);
    g_h1[row * 4 + b] = fmaxf(a, 0.0f);
}

// ---------------- generic fp32 warp-per-row matvec for 4 batches ----------------
__global__ void matvec4(const float* __restrict__ W, const float* __restrict__ bias,
                        const float* __restrict__ xin, float* __restrict__ yout,
                        int rows, int K, int relu) {
    int w = (blockIdx.x * blockDim.x + threadIdx.x) >> 5;
    int lane = threadIdx.x & 31;
    if (w >= rows) return;
    const float* Wr = W + (size_t)w * K;
    float a0 = 0.f, a1 = 0.f, a2 = 0.f, a3 = 0.f;
    for (int j = lane; j < K; j += 32) {
        float wv = Wr[j];
        float4 xv = reinterpret_cast<const float4*>(xin)[j];
        a0 = fmaf(wv, xv.x, a0); a1 = fmaf(wv, xv.y, a1);
        a2 = fmaf(wv, xv.z, a2); a3 = fmaf(wv, xv.w, a3);
    }
#pragma unroll
    for (int m = 16; m > 0; m >>= 1) {
        a0 += __shfl_xor_sync(0xffffffffu, a0, m);
        a1 += __shfl_xor_sync(0xffffffffu, a1, m);
        a2 += __shfl_xor_sync(0xffffffffu, a2, m);
        a3 += __shfl_xor_sync(0xffffffffu, a3, m);
    }
    if (lane == 0) {
        float bb = bias[w];
        a0 += bb; a1 += bb; a2 += bb; a3 += bb;
        if (relu) {
            a0 = fmaxf(a0, 0.f); a1 = fmaxf(a1, 0.f);
            a2 = fmaxf(a2, 0.f); a3 = fmaxf(a3, 0.f);
        }
        reinterpret_cast<float4*>(yout)[w] = make_float4(a0, a1, a2, a3);
    }
}

// ---------------- tiny root MLP: x_next_j = root_apply(theta_{j+1}, 2*t_j - t_{j-1}) ----------------
// Runs with 256 threads: thread = (batch b = tid/64, unit k = tid%64).
__device__ void root_apply(int j, const float* __restrict__ th,
                           const float* __restrict__ ts, float* __restrict__ out) {
    __shared__ float rh0[4][64];
    __shared__ float rh1[4][64];
    int tid = threadIdx.x;
    int b = tid >> 6, k = tid & 63;
    float tj  = ts[b * Tt + j];
    float tin = (j == 0) ? tj : (2.0f * tj - ts[b * Tt + j - 1]);
    float h = fmaf(th[k * 4 + b], tin, th[(64 + k) * 4 + b]);
    rh0[b][k] = fmaxf(h, 0.0f);
    __syncthreads();
    float a = th[(4224 + k) * 4 + b];
#pragma unroll 8
    for (int c = 0; c < 64; c++)
        a = fmaf(th[(128 + k * 64 + c) * 4 + b], rh0[b][c], a);
    rh1[b][k] = fmaxf(a, 0.0f);
    __syncthreads();
    if (k < 32) {
        float o = th[(6336 + k) * 4 + b];
#pragma unroll 8
        for (int c = 0; c < 64; c++)
            o = fmaf(th[(4288 + k * 64 + c) * 4 + b], rh1[b][c], o);
        float v;
        if (k < 16) {
            v = tanhf(o);
            g_xhat[j][b][k] = v;
        } else {
            v = fmaxf(o, 0.0f) + log1pf(expf(-fabsf(o)));  // softplus, stable
        }
        out[((size_t)b * Tt + j) * 32 + k] = v;
    }
}

// ---------------- per-step kernel: theta_{i+1} = 0.999*theta_i + E@theta_i + Bm@diff_i ----------------
// Block 0 : root MLP for step i-1 (reads theta_i only; output consumed 2 steps later).
// Blocks 1..100: 8 warps x 8-row tiles, theta staged in smem chunks, f32x2 FMAs.
__global__ void __launch_bounds__(256) step_kernel(int i, const float* __restrict__ xs,
                                                   const float* __restrict__ ts,
                                                   const float* __restrict__ Bm,
                                                   float* __restrict__ out) {
    const float* thin = g_theta[i & 1];
    if (blockIdx.x == 0) {
        if (i >= 1) root_apply(i - 1, thin, ts, out);
        return;
    }
    float* thout = g_theta[(i + 1) & 1];

    __shared__ float4 xsh[CHUNK];     // theta chunk, [j][b]
    __shared__ float  sdiff[17 * 4];  // diff per (component, batch)

    int tid = threadIdx.x;
    if (tid < 68) {
        int c = tid >> 2, b = tid & 3;
        float d;
        if (c == 0) {
            d = (i == 0) ? 0.0f : ts[b * Tt + i] - ts[b * Tt + i - 1];
        } else {
            float xt = xs[((size_t)b * Tt + i) * 16 + (c - 1)];
            float xp = (i < 2) ? xs[(size_t)b * Tt * 16 + (c - 1)]
                               : g_xhat[i - 2][b][c - 1];
            d = xt - xp;
        }
        sdiff[c * 4 + b] = d;
    }

    int warp = tid >> 5, lane = tid & 31;
    int tile = (blockIdx.x - 1) * 8 + warp;     // 8 rows per tile
    bool active = (tile < Ln / 8);

    unsigned long long acc[16];                 // acc[b*4 + pair]
#pragma unroll
    for (int q = 0; q < 16; q++) acc[q] = 0ull;

    const uint4* Ep = reinterpret_cast<const uint4*>(g_E) + (size_t)tile * Ln;

    for (int c0 = 0; c0 < Ln; c0 += CHUNK) {
        int len = min(CHUNK, Ln - c0);
        __syncthreads();
        const float4* tin4 = reinterpret_cast<const float4*>(thin) + c0;
        for (int jj = tid; jj < len; jj += 256) xsh[jj] = tin4[jj];
        __syncthreads();
        if (active) {
#pragma unroll 2
            for (int jj = lane; jj < len; jj += 32) {
                uint4 ev = Ep[c0 + jj];          // 8 fp16 rows at column j
                float4 xv = xsh[jj];             // theta[j][0..3]
                unsigned long long x0 = pk2(xv.x, xv.x);
                unsigned long long x1 = pk2(xv.y, xv.y);
                unsigned long long x2 = pk2(xv.z, xv.z);
                unsigned long long x3 = pk2(xv.w, xv.w);
                unsigned long long e0 = h2ff(ev.x);   // rows (0,1)
                unsigned long long e1 = h2ff(ev.y);   // rows (2,3)
                unsigned long long e2 = h2ff(ev.z);   // rows (4,5)
                unsigned long long e3 = h2ff(ev.w);   // rows (6,7)
                fma2(acc[0],  e0, x0); fma2(acc[1],  e1, x0);
                fma2(acc[2],  e2, x0); fma2(acc[3],  e3, x0);
                fma2(acc[4],  e0, x1); fma2(acc[5],  e1, x1);
                fma2(acc[6],  e2, x1); fma2(acc[7],  e3, x1);
                fma2(acc[8],  e0, x2); fma2(acc[9],  e1, x2);
                fma2(acc[10], e2, x2); fma2(acc[11], e3, x2);
                fma2(acc[12], e0, x3); fma2(acc[13], e1, x3);
                fma2(acc[14], e2, x3); fma2(acc[15], e3, x3);
            }
        }
    }
    if (!active) return;

#pragma unroll
    for (int q = 0; q < 16; q++) {
#pragma unroll
        for (int m = 16; m > 0; m >>= 1)
            acc[q] = add2(acc[q], __shfl_xor_sync(0xffffffffu, acc[q], m));
    }

    if (lane < 8) {
        int row = tile * 8 + lane;
        int p = lane >> 1, sel = lane & 1;
        const float* bmr = Bm + (size_t)row * 17;
        float bmv[17];
#pragma unroll
        for (int c = 0; c < 17; c++) bmv[c] = bmr[c];
        float4 told = reinterpret_cast<const float4*>(thin)[row];
        float to[4] = {told.x, told.y, told.z, told.w};
        float res[4];
#pragma unroll
        for (int b = 0; b < 4; b++) {
            float lo, hi;
            upk2(acc[b * 4 + p], lo, hi);
            float s = sel ? hi : lo;
            float y = fmaf(0.999f, to[b], s);
#pragma unroll
            for (int c = 0; c < 17; c++) y = fmaf(bmv[c], sdiff[c * 4 + b], y);
            res[b] = y;
        }
        reinterpret_cast<float4*>(thout)[row] = make_float4(res[0], res[1], res[2], res[3]);
    }
}

// ---------------- final root for step T-1 (needs theta_T, produced by last step kernel) ----------------
__global__ void root_final(const float* __restrict__ ts, float* __restrict__ out) {
    root_apply(Tt - 1, g_theta[Tt & 1], ts, out);   // theta_128 lives in buffer 0
}

// ---------------- launch ----------------
extern "C" void kernel_launch(void* const* d_in, const int* in_sizes, int n_in,
                              void* d_out, int out_size) {
    const float* xs = (const float*)d_in[0];
    const float* ts = (const float*)d_in[1];
    const float* A  = (const float*)d_in[2];
    const float* Bm = (const float*)d_in[3];
    const float* W1 = (const float*)d_in[4];
    const float* b1 = (const float*)d_in[5];
    const float* W2 = (const float*)d_in[6];
    const float* b2 = (const float*)d_in[7];
    const float* W3 = (const float*)d_in[8];
    const float* b3 = (const float*)d_in[9];
    // d_in[10] = seed: unused (FORCING_PROB == 1.0 makes the PRNG path dead)
    float* out = (float*)d_out;

    void *p_h1, *p_h2, *p_th;
    cudaGetSymbolAddress(&p_h1, g_h1);
    cudaGetSymbolAddress(&p_h2, g_h2);
    cudaGetSymbolAddress(&p_th, g_theta);   // g_theta[0]

    // Build packed fp16 E = A - 0.999 I  (re-done every launch: deterministic)
    size_t nq = (size_t)Ln * (Ln / 4);
    cvt_E<<<(unsigned)((nq + 255) / 256), 256>>>(A);

    // theta0 = W3 @ relu(W2 @ relu(W1 @ x0 + b1) + b2) + b3
    mlp1_kernel<<<(H1n * Bb + 255) / 256, 256>>>(W1, b1, xs);
    matvec4<<<(H2n * 32 + 255) / 256, 256>>>(W2, b2, (const float*)p_h1, (float*)p_h2, H2n, H1n, 1);
    matvec4<<<((size_t)Ln * 32 + 255) / 256, 256>>>(W3, b3, (const float*)p_h2, (float*)p_th, Ln, H2n, 0);

    // 128 sequential scan steps
    for (int i = 0; i < Tt; i++)
        step_kernel<<<101, 256>>>(i, xs, ts, Bm, out);

    root_final<<<1, 256>>>(ts, out);
}

// round 3
// speedup vs baseline: 1.9043x; 1.9043x over previous
#include <cuda_runtime.h>
#include <cuda_fp16.h>

#define Ln    6368
#define Tt    128
#define Bb    4
#define H1n   2133
#define H2n   4250
#define NT    398          // number of 16-wide tiles: 6368/16

// ---------------- device state (static allocations, allowed) ----------------
// E packed in mma-fragment order: g_Epk[((rt*NT + jt)*32 + lane)] is a uint4
// holding that lane's A-fragment {a0,a1,a2,a3} for tile (rt, jt).
__device__ __align__(16) uint4  g_Epk[(size_t)NT * NT * 32];
__device__ __align__(16) float  g_theta[2][Ln * Bb];      // fp32 theta, [j][b]
__device__ __align__(16) __half g_thh[2][4][Ln];          // fp16 theta, [b][j] (n-major)
__device__ __align__(16) float  g_h1[H1n * Bb];
__device__ __align__(16) float  g_h2[H2n * Bb];
__device__ __align__(16) float  g_xhat[Tt][Bb][16];       // tanh(mean) outputs per step

// ---------------- E conversion + fragment repack ----------------
// E = A - 0.999*I, fp16. Fragment layout for mma.m16n8k16 (A row-major):
//   a0 = E[r0][c0], E[r0][c0+1]        r0 = rt*16 + lane/4
//   a1 = E[r0+8][c0], E[r0+8][c0+1]    c0 = jt*16 + (lane%4)*2
//   a2 = E[r0][c0+8], E[r0][c0+9]
//   a3 = E[r0+8][c0+8], E[r0+8][c0+9]
__global__ void cvt_E_pack(const float* __restrict__ A) {
    size_t idx = (size_t)blockIdx.x * blockDim.x + threadIdx.x;
    if (idx >= (size_t)NT * NT * 32) return;
    int lane = (int)(idx & 31);
    size_t tIdx = idx >> 5;
    int rt = (int)(tIdx / NT), jt = (int)(tIdx % NT);
    int r0 = rt * 16 + (lane >> 2);
    int c0 = jt * 16 + (lane & 3) * 2;

    const float* Ar0 = A + (size_t)r0 * Ln;
    const float* Ar8 = A + (size_t)(r0 + 8) * Ln;
    float2 p00 = *reinterpret_cast<const float2*>(Ar0 + c0);
    float2 p10 = *reinterpret_cast<const float2*>(Ar8 + c0);
    float2 p01 = *reinterpret_cast<const float2*>(Ar0 + c0 + 8);
    float2 p11 = *reinterpret_cast<const float2*>(Ar8 + c0 + 8);
    // diagonal correction
    if (r0 == c0)         p00.x -= 0.999f;
    if (r0 == c0 + 1)     p00.y -= 0.999f;
    if (r0 + 8 == c0)     p10.x -= 0.999f;
    if (r0 + 8 == c0 + 1) p10.y -= 0.999f;
    if (r0 == c0 + 8)     p01.x -= 0.999f;
    if (r0 == c0 + 9)     p01.y -= 0.999f;
    if (r0 + 8 == c0 + 8) p11.x -= 0.999f;
    if (r0 + 8 == c0 + 9) p11.y -= 0.999f;

    __half2 h0 = __floats2half2_rn(p00.x, p00.y);
    __half2 h1 = __floats2half2_rn(p10.x, p10.y);
    __half2 h2 = __floats2half2_rn(p01.x, p01.y);
    __half2 h3 = __floats2half2_rn(p11.x, p11.y);
    uint4 v;
    v.x = *reinterpret_cast<unsigned*>(&h0);
    v.y = *reinterpret_cast<unsigned*>(&h1);
    v.z = *reinterpret_cast<unsigned*>(&h2);
    v.w = *reinterpret_cast<unsigned*>(&h3);
    g_Epk[idx] = v;
}

// ---------------- init MLP stage 1: h1 = relu(W1 @ xs[:,0] + b1) ----------------
__global__ void mlp1_kernel(const float* __restrict__ W1, const float* __restrict__ b1,
                            const float* __restrict__ xs) {
    int t = blockIdx.x * blockDim.x + threadIdx.x;
    if (t >= H1n * Bb) return;
    int row = t >> 2, b = t & 3;
    float a = b1[row];
    const float* x0 = xs + (size_t)b * Tt * 16;
#pragma unroll
    for (int d = 0; d < 16; d++) a = fmaf(W1[row * 16 + d], x0[d], a);
    g_h1[row * 4 + b] = fmaxf(a, 0.0f);
}

// ---------------- generic fp32 warp-per-row matvec for 4 batches ----------------
__global__ void matvec4(const float* __restrict__ W, const float* __restrict__ bias,
                        const float* __restrict__ xin, float* __restrict__ yout,
                        int rows, int K, int relu) {
    int w = (blockIdx.x * blockDim.x + threadIdx.x) >> 5;
    int lane = threadIdx.x & 31;
    if (w >= rows) return;
    const float* Wr = W + (size_t)w * K;
    float a0 = 0.f, a1 = 0.f, a2 = 0.f, a3 = 0.f;
    for (int j = lane; j < K; j += 32) {
        float wv = Wr[j];
        float4 xv = reinterpret_cast<const float4*>(xin)[j];
        a0 = fmaf(wv, xv.x, a0); a1 = fmaf(wv, xv.y, a1);
        a2 = fmaf(wv, xv.z, a2); a3 = fmaf(wv, xv.w, a3);
    }
#pragma unroll
    for (int m = 16; m > 0; m >>= 1) {
        a0 += __shfl_xor_sync(0xffffffffu, a0, m);
        a1 += __shfl_xor_sync(0xffffffffu, a1, m);
        a2 += __shfl_xor_sync(0xffffffffu, a2, m);
        a3 += __shfl_xor_sync(0xffffffffu, a3, m);
    }
    if (lane == 0) {
        float bb = bias[w];
        a0 += bb; a1 += bb; a2 += bb; a3 += bb;
        if (relu) {
            a0 = fmaxf(a0, 0.f); a1 = fmaxf(a1, 0.f);
            a2 = fmaxf(a2, 0.f); a3 = fmaxf(a3, 0.f);
        }
        reinterpret_cast<float4*>(yout)[w] = make_float4(a0, a1, a2, a3);
    }
}

// ---------------- theta0 fp32 -> fp16 transposed copy ----------------
__global__ void cvt_th0() {
    int t = blockIdx.x * blockDim.x + threadIdx.x;
    if (t >= Ln * Bb) return;
    int row = t >> 2, b = t & 3;
    g_thh[0][b][row] = __float2half(g_theta[0][row * 4 + b]);
}

// ---------------- tiny root MLP ----------------
__device__ void root_apply(int j, const float* __restrict__ th,
                           const float* __restrict__ ts, float* __restrict__ out) {
    __shared__ float rh0[4][64];
    __shared__ float rh1[4][64];
    int tid = threadIdx.x;
    int b = tid >> 6, k = tid & 63;
    float tj  = ts[b * Tt + j];
    float tin = (j == 0) ? tj : (2.0f * tj - ts[b * Tt + j - 1]);
    float h = fmaf(th[k * 4 + b], tin, th[(64 + k) * 4 + b]);
    rh0[b][k] = fmaxf(h, 0.0f);
    __syncthreads();
    float a = th[(4224 + k) * 4 + b];
#pragma unroll 8
    for (int c = 0; c < 64; c++)
        a = fmaf(th[(128 + k * 64 + c) * 4 + b], rh0[b][c], a);
    rh1[b][k] = fmaxf(a, 0.0f);
    __syncthreads();
    if (k < 32) {
        float o = th[(6336 + k) * 4 + b];
#pragma unroll 8
        for (int c = 0; c < 64; c++)
            o = fmaf(th[(4288 + k * 64 + c) * 4 + b], rh1[b][c], o);
        float v;
        if (k < 16) {
            v = tanhf(o);
            g_xhat[j][b][k] = v;
        } else {
            v = fmaxf(o, 0.0f) + log1pf(expf(-fabsf(o)));
        }
        out[((size_t)b * Tt + j) * 32 + k] = v;
    }
}

// ---------------- per-step kernel (HMMA version) ----------------
// Block 0: root MLP for step i-1. Blocks 1..199: 8 warps = 2 row-tiles x 4 K-quarters.
__global__ void __launch_bounds__(256) step_kernel(int i, const float* __restrict__ xs,
                                                   const float* __restrict__ ts,
                                                   const float* __restrict__ Bm,
                                                   float* __restrict__ out) {
    const float* thin = g_theta[i & 1];
    if (blockIdx.x == 0) {
        if (i >= 1) root_apply(i - 1, thin, ts, out);
        return;
    }
    float* thout = g_theta[(i + 1) & 1];
    const __half* thh_in = &g_thh[i & 1][0][0];
    __half* thh_out = &g_thh[(i + 1) & 1][0][0];

    __shared__ float sacc[2][4][16][8];
    __shared__ float sdiff[17 * 4];

    int tid = threadIdx.x;
    if (tid < 68) {
        int c = tid >> 2, b = tid & 3;
        float d;
        if (c == 0) {
            d = (i == 0) ? 0.0f : ts[b * Tt + i] - ts[b * Tt + i - 1];
        } else {
            float xt = xs[((size_t)b * Tt + i) * 16 + (c - 1)];
            float xp = (i < 2) ? xs[(size_t)b * Tt * 16 + (c - 1)]
                               : g_xhat[i - 2][b][c - 1];
            d = xt - xp;
        }
        sdiff[c * 4 + b] = d;
    }

    int lane = tid & 31, w = tid >> 5;
    int rl = w >> 2, kw = w & 3;                 // row-tile-local, K-quarter
    int rt = (blockIdx.x - 1) * 2 + rl;          // 0..397
    int jt0 = kw * 100;
    int jtN = min(jt0 + 100, NT) - jt0;          // 100,100,100,98

    const uint4* Ep = g_Epk + ((size_t)rt * NT + jt0) * 32 + lane;
    int n = lane >> 2;                           // B column (batch); n>=4 -> zero pad
    int k0 = (lane & 3) * 2;
    const __half* bn = thh_in + (size_t)n * Ln;  // g_thh[i&1][n][.]
    bool bvalid = (n < 4);

    float c0 = 0.f, c1 = 0.f, c2 = 0.f, c3 = 0.f;
#pragma unroll 4
    for (int it = 0; it < jtN; ++it) {
        uint4 af = Ep[(size_t)it * 32];
        unsigned b0 = 0u, b1 = 0u;
        if (bvalid) {
            int jj = (jt0 + it) * 16 + k0;
            b0 = *reinterpret_cast<const unsigned*>(bn + jj);
            b1 = *reinterpret_cast<const unsigned*>(bn + jj + 8);
        }
        asm volatile(
            "mma.sync.aligned.m16n8k16.row.col.f32.f16.f16.f32 "
            "{%0,%1,%2,%3}, {%4,%5,%6,%7}, {%8,%9}, {%0,%1,%2,%3};"
            : "+f"(c0), "+f"(c1), "+f"(c2), "+f"(c3)
            : "r"(af.x), "r"(af.y), "r"(af.z), "r"(af.w), "r"(b0), "r"(b1));
    }

    // D layout: c0/c1 at (row=lane/4, col=2*(lane%4)+{0,1}); c2/c3 at row+8.
    {
        int r = lane >> 2, cc = (lane & 3) * 2;
        sacc[rl][kw][r][cc]         = c0;
        sacc[rl][kw][r][cc + 1]     = c1;
        sacc[rl][kw][r + 8][cc]     = c2;
        sacc[rl][kw][r + 8][cc + 1] = c3;
    }
    __syncthreads();

    if (tid < 128) {
        int rl2 = tid >> 6, rr = (tid >> 2) & 15, b = tid & 3;
        float v = sacc[rl2][0][rr][b] + sacc[rl2][1][rr][b]
                + sacc[rl2][2][rr][b] + sacc[rl2][3][rr][b];
        int row = ((blockIdx.x - 1) * 2 + rl2) * 16 + rr;
        float y = fmaf(0.999f, thin[row * 4 + b], v);
        const float* bmr = Bm + (size_t)row * 17;
#pragma unroll
        for (int c = 0; c < 17; c++) y = fmaf(bmr[c], sdiff[c * 4 + b], y);
        thout[row * 4 + b] = y;
        thh_out[(size_t)b * Ln + row] = __float2half(y);
    }
}

// ---------------- final root for step T-1 ----------------
__global__ void root_final(const float* __restrict__ ts, float* __restrict__ out) {
    root_apply(Tt - 1, g_theta[Tt & 1], ts, out);
}

// ---------------- launch ----------------
extern "C" void kernel_launch(void* const* d_in, const int* in_sizes, int n_in,
                              void* d_out, int out_size) {
    const float* xs = (const float*)d_in[0];
    const float* ts = (const float*)d_in[1];
    const float* A  = (const float*)d_in[2];
    const float* Bm = (const float*)d_in[3];
    const float* W1 = (const float*)d_in[4];
    const float* b1 = (const float*)d_in[5];
    const float* W2 = (const float*)d_in[6];
    const float* b2 = (const float*)d_in[7];
    const float* W3 = (const float*)d_in[8];
    const float* b3 = (const float*)d_in[9];
    // d_in[10] = seed: dead (FORCING_PROB == 1.0)
    float* out = (float*)d_out;

    void *p_h1, *p_h2, *p_th;
    cudaGetSymbolAddress(&p_h1, g_h1);
    cudaGetSymbolAddress(&p_h2, g_h2);
    cudaGetSymbolAddress(&p_th, g_theta);   // g_theta[0]

    // Pack E = A - 0.999 I into fp16 mma-fragment layout.
    size_t npk = (size_t)NT * NT * 32;
    cvt_E_pack<<<(unsigned)((npk + 255) / 256), 256>>>(A);

    // theta0 = W3 @ relu(W2 @ relu(W1 @ x0 + b1) + b2) + b3
    mlp1_kernel<<<(H1n * Bb + 255) / 256, 256>>>(W1, b1, xs);
    matvec4<<<(H2n * 32 + 255) / 256, 256>>>(W2, b2, (const float*)p_h1, (float*)p_h2, H2n, H1n, 1);
    matvec4<<<((size_t)Ln * 32 + 255) / 256, 256>>>(W3, b3, (const float*)p_h2, (float*)p_th, Ln, H2n, 0);
    cvt_th0<<<(Ln * Bb + 255) / 256, 256>>>();

    // 128 sequential scan steps
    for (int i = 0; i < Tt; i++)
        step_kernel<<<200, 256>>>(i, xs, ts, Bm, out);

    root_final<<<1, 256>>>(ts, out);
}

// round 4
// speedup vs baseline: 1.9816x; 1.0406x over previous
#include <cuda_runtime.h>
#include <cuda_fp16.h>

#define Ln    6368
#define Tt    128
#define Bb    4
#define H1n   2133
#define H2n   4250
#define NT    398          // number of 16-wide tiles: 6368/16

// ---------------- device state (static allocations, allowed) ----------------
// E packed in mma-fragment order: g_Epk[((rt*NT + jt)*32 + lane)] is a uint4
// holding that lane's A-fragment {a0,a1,a2,a3} for tile (rt, jt).
__device__ __align__(16) uint4  g_Epk[(size_t)NT * NT * 32];
__device__ __align__(16) float  g_theta[2][Ln * Bb];      // fp32 theta, [j][b]
__device__ __align__(16) __half g_thh[2][4][Ln];          // fp16 theta, [b][j] (n-major)
__device__ __align__(16) float  g_h1[H1n * Bb];
__device__ __align__(16) float  g_h2[H2n * Bb];
__device__ __align__(16) float  g_xhat[Tt][Bb][16];       // tanh(mean) outputs per step

// ---------------- E conversion + fragment repack ----------------
// E = A - 0.999*I, fp16. Fragment layout for mma.m16n8k16 (A row-major):
//   a0 = E[r0][c0], E[r0][c0+1]        r0 = rt*16 + lane/4
//   a1 = E[r0+8][c0], E[r0+8][c0+1]    c0 = jt*16 + (lane%4)*2
//   a2 = E[r0][c0+8], E[r0][c0+9]
//   a3 = E[r0+8][c0+8], E[r0+8][c0+9]
__global__ void cvt_E_pack(const float* __restrict__ A) {
    size_t idx = (size_t)blockIdx.x * blockDim.x + threadIdx.x;
    if (idx >= (size_t)NT * NT * 32) return;
    int lane = (int)(idx & 31);
    size_t tIdx = idx >> 5;
    int rt = (int)(tIdx / NT), jt = (int)(tIdx % NT);
    int r0 = rt * 16 + (lane >> 2);
    int c0 = jt * 16 + (lane & 3) * 2;

    const float* Ar0 = A + (size_t)r0 * Ln;
    const float* Ar8 = A + (size_t)(r0 + 8) * Ln;
    float2 p00 = *reinterpret_cast<const float2*>(Ar0 + c0);
    float2 p10 = *reinterpret_cast<const float2*>(Ar8 + c0);
    float2 p01 = *reinterpret_cast<const float2*>(Ar0 + c0 + 8);
    float2 p11 = *reinterpret_cast<const float2*>(Ar8 + c0 + 8);
    // diagonal correction
    if (r0 == c0)         p00.x -= 0.999f;
    if (r0 == c0 + 1)     p00.y -= 0.999f;
    if (r0 + 8 == c0)     p10.x -= 0.999f;
    if (r0 + 8 == c0 + 1) p10.y -= 0.999f;
    if (r0 == c0 + 8)     p01.x -= 0.999f;
    if (r0 == c0 + 9)     p01.y -= 0.999f;
    if (r0 + 8 == c0 + 8) p11.x -= 0.999f;
    if (r0 + 8 == c0 + 9) p11.y -= 0.999f;

    __half2 h0 = __floats2half2_rn(p00.x, p00.y);
    __half2 h1 = __floats2half2_rn(p10.x, p10.y);
    __half2 h2 = __floats2half2_rn(p01.x, p01.y);
    __half2 h3 = __floats2half2_rn(p11.x, p11.y);
    uint4 v;
    v.x = *reinterpret_cast<unsigned*>(&h0);
    v.y = *reinterpret_cast<unsigned*>(&h1);
    v.z = *reinterpret_cast<unsigned*>(&h2);
    v.w = *reinterpret_cast<unsigned*>(&h3);
    g_Epk[idx] = v;
}

// ---------------- init MLP stage 1: h1 = relu(W1 @ xs[:,0] + b1) ----------------
__global__ void mlp1_kernel(const float* __restrict__ W1, const float* __restrict__ b1,
                            const float* __restrict__ xs) {
    int t = blockIdx.x * blockDim.x + threadIdx.x;
    if (t >= H1n * Bb) return;
    int row = t >> 2, b = t & 3;
    float a = b1[row];
    const float* x0 = xs + (size_t)b * Tt * 16;
#pragma unroll
    for (int d = 0; d < 16; d++) a = fmaf(W1[row * 16 + d], x0[d], a);
    g_h1[row * 4 + b] = fmaxf(a, 0.0f);
}

// ---------------- generic fp32 warp-per-row matvec for 4 batches ----------------
__global__ void matvec4(const float* __restrict__ W, const float* __restrict__ bias,
                        const float* __restrict__ xin, float* __restrict__ yout,
                        int rows, int K, int relu) {
    int w = (blockIdx.x * blockDim.x + threadIdx.x) >> 5;
    int lane = threadIdx.x & 31;
    if (w >= rows) return;
    const float* Wr = W + (size_t)w * K;
    float a0 = 0.f, a1 = 0.f, a2 = 0.f, a3 = 0.f;
    for (int j = lane; j < K; j += 32) {
        float wv = Wr[j];
        float4 xv = reinterpret_cast<const float4*>(xin)[j];
        a0 = fmaf(wv, xv.x, a0); a1 = fmaf(wv, xv.y, a1);
        a2 = fmaf(wv, xv.z, a2); a3 = fmaf(wv, xv.w, a3);
    }
#pragma unroll
    for (int m = 16; m > 0; m >>= 1) {
        a0 += __shfl_xor_sync(0xffffffffu, a0, m);
        a1 += __shfl_xor_sync(0xffffffffu, a1, m);
        a2 += __shfl_xor_sync(0xffffffffu, a2, m);
        a3 += __shfl_xor_sync(0xffffffffu, a3, m);
    }
    if (lane == 0) {
        float bb = bias[w];
        a0 += bb; a1 += bb; a2 += bb; a3 += bb;
        if (relu) {
            a0 = fmaxf(a0, 0.f); a1 = fmaxf(a1, 0.f);
            a2 = fmaxf(a2, 0.f); a3 = fmaxf(a3, 0.f);
        }
        reinterpret_cast<float4*>(yout)[w] = make_float4(a0, a1, a2, a3);
    }
}

// ---------------- theta0 fp32 -> fp16 transposed copy ----------------
__global__ void cvt_th0() {
    int t = blockIdx.x * blockDim.x + threadIdx.x;
    if (t >= Ln * Bb) return;
    int row = t >> 2, b = t & 3;
    g_thh[0][b][row] = __float2half(g_theta[0][row * 4 + b]);
}

// ---------------- tiny root MLP ----------------
__device__ void root_apply(int j, const float* __restrict__ th,
                           const float* __restrict__ ts, float* __restrict__ out) {
    __shared__ float rh0[4][64];
    __shared__ float rh1[4][64];
    int tid = threadIdx.x;
    int b = tid >> 6, k = tid & 63;
    float tj  = ts[b * Tt + j];
    float tin = (j == 0) ? tj : (2.0f * tj - ts[b * Tt + j - 1]);
    float h = fmaf(th[k * 4 + b], tin, th[(64 + k) * 4 + b]);
    rh0[b][k] = fmaxf(h, 0.0f);
    __syncthreads();
    float a = th[(4224 + k) * 4 + b];
#pragma unroll 8
    for (int c = 0; c < 64; c++)
        a = fmaf(th[(128 + k * 64 + c) * 4 + b], rh0[b][c], a);
    rh1[b][k] = fmaxf(a, 0.0f);
    __syncthreads();
    if (k < 32) {
        float o = th[(6336 + k) * 4 + b];
#pragma unroll 8
        for (int c = 0; c < 64; c++)
            o = fmaf(th[(4288 + k * 64 + c) * 4 + b], rh1[b][c], o);
        float v;
        if (k < 16) {
            v = tanhf(o);
            g_xhat[j][b][k] = v;
        } else {
            v = fmaxf(o, 0.0f) + log1pf(expf(-fabsf(o)));
        }
        out[((size_t)b * Tt + j) * 32 + k] = v;
    }
}

// ---------------- per-step kernel (HMMA version) ----------------
// Block 0: root MLP for step i-1. Blocks 1..199: 8 warps = 2 row-tiles x 4 K-quarters.
__global__ void __launch_bounds__(256) step_kernel(int i, const float* __restrict__ xs,
                                                   const float* __restrict__ ts,
                                                   const float* __restrict__ Bm,
                                                   float* __restrict__ out) {
    const float* thin = g_theta[i & 1];
    if (blockIdx.x == 0) {
        if (i >= 1) root_apply(i - 1, thin, ts, out);
        return;
    }
    float* thout = g_theta[(i + 1) & 1];
    const __half* thh_in = &g_thh[i & 1][0][0];
    __half* thh_out = &g_thh[(i + 1) & 1][0][0];

    __shared__ float sacc[2][4][16][8];
    __shared__ float sdiff[17 * 4];

    int tid = threadIdx.x;
    if (tid < 68) {
        int c = tid >> 2, b = tid & 3;
        float d;
        if (c == 0) {
            d = (i == 0) ? 0.0f : ts[b * Tt + i] - ts[b * Tt + i - 1];
        } else {
            float xt = xs[((size_t)b * Tt + i) * 16 + (c - 1)];
            float xp = (i < 2) ? xs[(size_t)b * Tt * 16 + (c - 1)]
                               : g_xhat[i - 2][b][c - 1];
            d = xt - xp;
        }
        sdiff[c * 4 + b] = d;
    }

    int lane = tid & 31, w = tid >> 5;
    int rl = w >> 2, kw = w & 3;                 // row-tile-local, K-quarter
    int rt = (blockIdx.x - 1) * 2 + rl;          // 0..397
    int jt0 = kw * 100;
    int jtN = min(jt0 + 100, NT) - jt0;          // 100,100,100,98

    const uint4* Ep = g_Epk + ((size_t)rt * NT + jt0) * 32 + lane;
    int n = lane >> 2;                           // B column (batch); n>=4 -> zero pad
    int k0 = (lane & 3) * 2;
    const __half* bn = thh_in + (size_t)n * Ln;  // g_thh[i&1][n][.]
    bool bvalid = (n < 4);

    float c0 = 0.f, c1 = 0.f, c2 = 0.f, c3 = 0.f;
#pragma unroll 4
    for (int it = 0; it < jtN; ++it) {
        uint4 af = Ep[(size_t)it * 32];
        unsigned b0 = 0u, b1 = 0u;
        if (bvalid) {
            int jj = (jt0 + it) * 16 + k0;
            b0 = *reinterpret_cast<const unsigned*>(bn + jj);
            b1 = *reinterpret_cast<const unsigned*>(bn + jj + 8);
        }
        asm volatile(
            "mma.sync.aligned.m16n8k16.row.col.f32.f16.f16.f32 "
            "{%0,%1,%2,%3}, {%4,%5,%6,%7}, {%8,%9}, {%0,%1,%2,%3};"
            : "+f"(c0), "+f"(c1), "+f"(c2), "+f"(c3)
            : "r"(af.x), "r"(af.y), "r"(af.z), "r"(af.w), "r"(b0), "r"(b1));
    }

    // D layout: c0/c1 at (row=lane/4, col=2*(lane%4)+{0,1}); c2/c3 at row+8.
    {
        int r = lane >> 2, cc = (lane & 3) * 2;
        sacc[rl][kw][r][cc]         = c0;
        sacc[rl][kw][r][cc + 1]     = c1;
        sacc[rl][kw][r + 8][cc]     = c2;
        sacc[rl][kw][r + 8][cc + 1] = c3;
    }
    __syncthreads();

    if (tid < 128) {
        int rl2 = tid >> 6, rr = (tid >> 2) & 15, b = tid & 3;
        float v = sacc[rl2][0][rr][b] + sacc[rl2][1][rr][b]
                + sacc[rl2][2][rr][b] + sacc[rl2][3][rr][b];
        int row = ((blockIdx.x - 1) * 2 + rl2) * 16 + rr;
        float y = fmaf(0.999f, thin[row * 4 + b], v);
        const float* bmr = Bm + (size_t)row * 17;
#pragma unroll
        for (int c = 0; c < 17; c++) y = fmaf(bmr[c], sdiff[c * 4 + b], y);
        thout[row * 4 + b] = y;
        thh_out[(size_t)b * Ln + row] = __float2half(y);
    }
}

// ---------------- final root for step T-1 ----------------
__global__ void root_final(const float* __restrict__ ts, float* __restrict__ out) {
    root_apply(Tt - 1, g_theta[Tt & 1], ts, out);
}

// ---------------- launch ----------------
extern "C" void kernel_launch(void* const* d_in, const int* in_sizes, int n_in,
                              void* d_out, int out_size) {
    const float* xs = (const float*)d_in[0];
    const float* ts = (const float*)d_in[1];
    const float* A  = (const float*)d_in[2];
    const float* Bm = (const float*)d_in[3];
    const float* W1 = (const float*)d_in[4];
    const float* b1 = (const float*)d_in[5];
    const float* W2 = (const float*)d_in[6];
    const float* b2 = (const float*)d_in[7];
    const float* W3 = (const float*)d_in[8];
    const float* b3 = (const float*)d_in[9];
    // d_in[10] = seed: dead (FORCING_PROB == 1.0)
    float* out = (float*)d_out;

    void *p_h1, *p_h2, *p_th;
    cudaGetSymbolAddress(&p_h1, g_h1);
    cudaGetSymbolAddress(&p_h2, g_h2);
    cudaGetSymbolAddress(&p_th, g_theta);   // g_theta[0]

    // Pack E = A - 0.999 I into fp16 mma-fragment layout.
    size_t npk = (size_t)NT * NT * 32;
    cvt_E_pack<<<(unsigned)((npk + 255) / 256), 256>>>(A);

    // theta0 = W3 @ relu(W2 @ relu(W1 @ x0 + b1) + b2) + b3
    mlp1_kernel<<<(H1n * Bb + 255) / 256, 256>>>(W1, b1, xs);
    matvec4<<<(H2n * 32 + 255) / 256, 256>>>(W2, b2, (const float*)p_h1, (float*)p_h2, H2n, H1n, 1);
    matvec4<<<((size_t)Ln * 32 + 255) / 256, 256>>>(W3, b3, (const float*)p_h2, (float*)p_th, Ln, H2n, 0);
    cvt_th0<<<(Ln * Bb + 255) / 256, 256>>>();

    // 128 sequential scan steps
    for (int i = 0; i < Tt; i++)
        step_kernel<<<200, 256>>>(i, xs, ts, Bm, out);

    root_final<<<1, 256>>>(ts, out);
}

// round 5
// speedup vs baseline: 3.1070x; 1.5679x over previous
#include <cuda_runtime.h>
#include <cuda_fp16.h>
#include <cstdint>

#define Ln    6368
#define Tt    128
#define H1n   2133
#define H2n   4250
#define NT    398          // 16-row tiles: 6368/16
#define CgT   5            // fragment-tiles per TMA group (5*512B = 2560B)
#define TPW   50           // k-tiles per warp (warp 7 gets 48)

// dynamic smem layout (per block)
#define SM_TH    0                    // fp16 theta [4][Ln] = 50944 B
#define SM_EBUF  51200                // 8 warps * 2 stages * CgT*512 = 40960 B
#define SM_MBAR  (51200 + 40960)      // 16 mbarriers * 8 B = 128 B
#define SM_DYN   (SM_MBAR + 128)      // 92288 B

// ---------------- device state ----------------
__device__ __align__(16) uint4  g_Epk[(size_t)NT * NT * 32];   // E fragments, 81 MB
__device__ __align__(16) float  g_theta[2][Ln * 4];            // fp32 theta [j][b]
__device__ __align__(16) __half g_thh[2][4][Ln];               // fp16 theta [b][j]
__device__ __align__(16) float  g_h1[H1n * 4];
__device__ __align__(16) float  g_h2[H2n * 4];
__device__ __align__(16) float  g_xhat[Tt][4][16];

// ---------------- helpers ----------------
__device__ __forceinline__ uint32_t s2u(const void* p) {
    uint32_t a;
    asm("{ .reg .u64 t; cvta.to.shared.u64 t, %1; cvt.u32.u64 %0, t; }" : "=r"(a) : "l"(p));
    return a;
}
#define MBAR_INIT(a, n) asm volatile("mbarrier.init.shared.b64 [%0], %1;" :: "r"(a), "r"(n) : "memory")
#define MBAR_EXPECT(a, b) asm volatile("mbarrier.arrive.expect_tx.shared.b64 _, [%0], %1;" :: "r"(a), "r"(b) : "memory")
#define MBAR_WAIT(a, p) asm volatile( \
    "{\n\t.reg .pred P1;\nWL_%=:\n\t" \
    "mbarrier.try_wait.parity.acquire.cta.shared::cta.b64 P1, [%0], %1, 0x989680;\n\t" \
    "@P1 bra.uni WD_%=;\n\tbra.uni WL_%=;\nWD_%=:\n\t}" \
    :: "r"(a), "r"(p) : "memory")

// ---------------- E conversion + fragment repack ----------------
__global__ void cvt_E_pack(const float* __restrict__ A) {
    size_t idx = (size_t)blockIdx.x * blockDim.x + threadIdx.x;
    if (idx >= (size_t)NT * NT * 32) return;
    int lane = (int)(idx & 31);
    size_t tIdx = idx >> 5;
    int rt = (int)(tIdx / NT), jt = (int)(tIdx % NT);
    int r0 = rt * 16 + (lane >> 2);
    int c0 = jt * 16 + (lane & 3) * 2;
    const float* Ar0 = A + (size_t)r0 * Ln;
    const float* Ar8 = A + (size_t)(r0 + 8) * Ln;
    float2 p00 = *reinterpret_cast<const float2*>(Ar0 + c0);
    float2 p10 = *reinterpret_cast<const float2*>(Ar8 + c0);
    float2 p01 = *reinterpret_cast<const float2*>(Ar0 + c0 + 8);
    float2 p11 = *reinterpret_cast<const float2*>(Ar8 + c0 + 8);
    if (r0 == c0)         p00.x -= 0.999f;
    if (r0 == c0 + 1)     p00.y -= 0.999f;
    if (r0 + 8 == c0)     p10.x -= 0.999f;
    if (r0 + 8 == c0 + 1) p10.y -= 0.999f;
    if (r0 == c0 + 8)     p01.x -= 0.999f;
    if (r0 == c0 + 9)     p01.y -= 0.999f;
    if (r0 + 8 == c0 + 8) p11.x -= 0.999f;
    if (r0 + 8 == c0 + 9) p11.y -= 0.999f;
    __half2 h0 = __floats2half2_rn(p00.x, p00.y);
    __half2 h1 = __floats2half2_rn(p10.x, p10.y);
    __half2 h2 = __floats2half2_rn(p01.x, p01.y);
    __half2 h3 = __floats2half2_rn(p11.x, p11.y);
    uint4 v;
    v.x = *reinterpret_cast<unsigned*>(&h0);
    v.y = *reinterpret_cast<unsigned*>(&h1);
    v.z = *reinterpret_cast<unsigned*>(&h2);
    v.w = *reinterpret_cast<unsigned*>(&h3);
    g_Epk[idx] = v;
}

// ---------------- init MLP ----------------
__global__ void mlp1_kernel(const float* __restrict__ W1, const float* __restrict__ b1,
                            const float* __restrict__ xs) {
    int t = blockIdx.x * blockDim.x + threadIdx.x;
    if (t >= H1n * 4) return;
    int row = t >> 2, b = t & 3;
    float a = b1[row];
    const float* x0 = xs + (size_t)b * Tt * 16;
#pragma unroll
    for (int d = 0; d < 16; d++) a = fmaf(W1[row * 16 + d], x0[d], a);
    g_h1[row * 4 + b] = fmaxf(a, 0.0f);
}

__global__ void matvec4(const float* __restrict__ W, const float* __restrict__ bias,
                        const float* __restrict__ xin, float* __restrict__ yout,
                        int rows, int K, int relu) {
    int w = (blockIdx.x * blockDim.x + threadIdx.x) >> 5;
    int lane = threadIdx.x & 31;
    if (w >= rows) return;
    const float* Wr = W + (size_t)w * K;
    float a0 = 0.f, a1 = 0.f, a2 = 0.f, a3 = 0.f;
#pragma unroll 4
    for (int j = lane; j < K; j += 32) {
        float wv = Wr[j];
        float4 xv = reinterpret_cast<const float4*>(xin)[j];
        a0 = fmaf(wv, xv.x, a0); a1 = fmaf(wv, xv.y, a1);
        a2 = fmaf(wv, xv.z, a2); a3 = fmaf(wv, xv.w, a3);
    }
#pragma unroll
    for (int m = 16; m > 0; m >>= 1) {
        a0 += __shfl_xor_sync(0xffffffffu, a0, m);
        a1 += __shfl_xor_sync(0xffffffffu, a1, m);
        a2 += __shfl_xor_sync(0xffffffffu, a2, m);
        a3 += __shfl_xor_sync(0xffffffffu, a3, m);
    }
    if (lane == 0) {
        float bb = bias[w];
        a0 += bb; a1 += bb; a2 += bb; a3 += bb;
        if (relu) {
            a0 = fmaxf(a0, 0.f); a1 = fmaxf(a1, 0.f);
            a2 = fmaxf(a2, 0.f); a3 = fmaxf(a3, 0.f);
        }
        reinterpret_cast<float4*>(yout)[w] = make_float4(a0, a1, a2, a3);
    }
}

__global__ void cvt_th0() {
    int t = blockIdx.x * blockDim.x + threadIdx.x;
    if (t >= Ln * 4) return;
    int row = t >> 2, b = t & 3;
    g_thh[0][b][row] = __float2half(g_theta[0][row * 4 + b]);
}

// ---------------- tiny root MLP ----------------
__device__ void root_apply(int j, const float* __restrict__ th,
                           const float* __restrict__ ts, float* __restrict__ out) {
    __shared__ float rh0[4][64];
    __shared__ float rh1[4][64];
    int tid = threadIdx.x;
    int b = tid >> 6, k = tid & 63;
    float tj  = ts[b * Tt + j];
    float tin = (j == 0) ? tj : (2.0f * tj - ts[b * Tt + j - 1]);
    float h = fmaf(th[k * 4 + b], tin, th[(64 + k) * 4 + b]);
    rh0[b][k] = fmaxf(h, 0.0f);
    __syncthreads();
    float a = th[(4224 + k) * 4 + b];
#pragma unroll 8
    for (int c = 0; c < 64; c++)
        a = fmaf(th[(128 + k * 64 + c) * 4 + b], rh0[b][c], a);
    rh1[b][k] = fmaxf(a, 0.0f);
    __syncthreads();
    if (k < 32) {
        float o = th[(6336 + k) * 4 + b];
#pragma unroll 8
        for (int c = 0; c < 64; c++)
            o = fmaf(th[(4288 + k * 64 + c) * 4 + b], rh1[b][c], o);
        float v;
        if (k < 16) {
            v = tanhf(o);
            g_xhat[j][b][k] = v;
        } else {
            v = fmaxf(o, 0.0f) + log1pf(expf(-fabsf(o)));
        }
        out[((size_t)b * Tt + j) * 32 + k] = v;
    }
}

// ---------------- per-step kernel: TMA-staged HMMA ----------------
// Block 0: root MLP for step i-1. Blocks 1..398: row-tile rt = blockIdx-1,
// 8 warps = 8-way K split, E streamed via cp.async.bulk double-buffering.
__global__ void __launch_bounds__(256, 2) step_kernel(int i, const float* __restrict__ xs,
                                                      const float* __restrict__ ts,
                                                      const float* __restrict__ Bm,
                                                      float* __restrict__ out) {
    const float* thin = g_theta[i & 1];
    if (blockIdx.x == 0) {
        if (i >= 1) root_apply(i - 1, thin, ts, out);
        return;
    }
    extern __shared__ __align__(1024) char dsm[];
    __half* th_s = reinterpret_cast<__half*>(dsm);
    uint32_t smem_base = s2u(dsm);
    uint32_t mbar_base = smem_base + SM_MBAR;

    __shared__ float sacc[8][16][8];
    __shared__ float sdiff[17 * 4];

    int tid = threadIdx.x, lane = tid & 31, w = tid >> 5;
    int rt = blockIdx.x - 1;

    // stage fp16 theta (all 4 batches) into smem
    {
        const uint4* src = reinterpret_cast<const uint4*>(&g_thh[i & 1][0][0]);
        uint4* dst = reinterpret_cast<uint4*>(th_s);
        for (int k = tid; k < (4 * Ln * 2) / 16; k += 256) dst[k] = src[k];
    }
    if (tid < 16) MBAR_INIT(mbar_base + tid * 8, 1);
    if (tid < 68) {
        int c = tid >> 2, b = tid & 3;
        float d;
        if (c == 0) {
            d = (i == 0) ? 0.0f : ts[b * Tt + i] - ts[b * Tt + i - 1];
        } else {
            float xt = xs[((size_t)b * Tt + i) * 16 + (c - 1)];
            float xp = (i < 2) ? xs[(size_t)b * Tt * 16 + (c - 1)]
                               : g_xhat[i - 2][b][c - 1];
            d = xt - xp;
        }
        sdiff[c * 4 + b] = d;
    }
    __syncthreads();

    int jt0 = w * TPW;
    int jtN = min(TPW, NT - jt0);                 // 50 (warp7: 48)
    int ngroups = (jtN + CgT - 1) / CgT;          // 10
    const char* esrc = reinterpret_cast<const char*>(g_Epk) + ((size_t)rt * NT + jt0) * 512;
    uint32_t mybar = mbar_base + w * 16;
    uint32_t mybuf = smem_base + SM_EBUF + w * (2 * CgT * 512);

    // issue group g into stage (g&1)
#define ISSUE(g) do { \
        int _g = (g); \
        if (_g < ngroups && lane == 0) { \
            int _t0 = _g * CgT; \
            unsigned _bytes = (unsigned)(min(CgT, jtN - _t0) * 512); \
            uint32_t _mb = mybar + (_g & 1) * 8; \
            uint32_t _db = mybuf + (_g & 1) * (CgT * 512); \
            MBAR_EXPECT(_mb, _bytes); \
            asm volatile("cp.async.bulk.shared::cta.global.mbarrier::complete_tx::bytes [%0], [%1], %2, [%3];" \
                         :: "r"(_db), "l"(esrc + (size_t)_t0 * 512), "r"(_bytes), "r"(_mb) : "memory"); \
        } \
    } while (0)

    ISSUE(0);
    ISSUE(1);

    float c0 = 0.f, c1 = 0.f, c2 = 0.f, c3 = 0.f;
    int n = lane >> 2, k0 = (lane & 3) * 2;
    const __half* bn = th_s + n * Ln;
    bool bvalid = (n < 4);

    for (int g = 0; g < ngroups; g++) {
        int s = g & 1, ph = (g >> 1) & 1;
        MBAR_WAIT(mybar + s * 8, ph);
        int t0 = g * CgT;
        int nt = min(CgT, jtN - t0);
        uint32_t bufb = mybuf + s * (CgT * 512) + lane * 16;
#pragma unroll
        for (int t = 0; t < CgT; t++) {
            if (t >= nt) break;
            uint4 af;
            asm volatile("ld.shared.v4.u32 {%0,%1,%2,%3}, [%4];"
                         : "=r"(af.x), "=r"(af.y), "=r"(af.z), "=r"(af.w)
                         : "r"(bufb + t * 512));
            unsigned b0 = 0u, b1 = 0u;
            if (bvalid) {
                int jj = (jt0 + t0 + t) * 16 + k0;
                b0 = *reinterpret_cast<const unsigned*>(bn + jj);
                b1 = *reinterpret_cast<const unsigned*>(bn + jj + 8);
            }
            asm volatile(
                "mma.sync.aligned.m16n8k16.row.col.f32.f16.f16.f32 "
                "{%0,%1,%2,%3}, {%4,%5,%6,%7}, {%8,%9}, {%0,%1,%2,%3};"
                : "+f"(c0), "+f"(c1), "+f"(c2), "+f"(c3)
                : "r"(af.x), "r"(af.y), "r"(af.z), "r"(af.w), "r"(b0), "r"(b1));
        }
        __syncwarp();
        if (lane == 0) asm volatile("fence.proxy.async.shared::cta;" ::: "memory");
        ISSUE(g + 2);
    }
#undef ISSUE

    {
        int r = lane >> 2, cc = (lane & 3) * 2;
        sacc[w][r][cc]         = c0;
        sacc[w][r][cc + 1]     = c1;
        sacc[w][r + 8][cc]     = c2;
        sacc[w][r + 8][cc + 1] = c3;
    }
    __syncthreads();

    if (tid < 64) {
        int rr = tid >> 2, b = tid & 3;
        float v = 0.f;
#pragma unroll
        for (int kw = 0; kw < 8; kw++) v += sacc[kw][rr][b];
        int row = rt * 16 + rr;
        float y = fmaf(0.999f, thin[row * 4 + b], v);
        const float* bmr = Bm + (size_t)row * 17;
#pragma unroll
        for (int c = 0; c < 17; c++) y = fmaf(bmr[c], sdiff[c * 4 + b], y);
        g_theta[(i + 1) & 1][row * 4 + b] = y;
        g_thh[(i + 1) & 1][b][row] = __float2half(y);
    }
}

// ---------------- final root for step T-1 ----------------
__global__ void root_final(const float* __restrict__ ts, float* __restrict__ out) {
    root_apply(Tt - 1, g_theta[Tt & 1], ts, out);
}

// ---------------- launch ----------------
extern "C" void kernel_launch(void* const* d_in, const int* in_sizes, int n_in,
                              void* d_out, int out_size) {
    const float* xs = (const float*)d_in[0];
    const float* ts = (const float*)d_in[1];
    const float* A  = (const float*)d_in[2];
    const float* Bm = (const float*)d_in[3];
    const float* W1 = (const float*)d_in[4];
    const float* b1 = (const float*)d_in[5];
    const float* W2 = (const float*)d_in[6];
    const float* b2 = (const float*)d_in[7];
    const float* W3 = (const float*)d_in[8];
    const float* b3 = (const float*)d_in[9];
    // d_in[10] = seed: dead (FORCING_PROB == 1.0)
    float* out = (float*)d_out;

    static bool attr_done = false;
    if (!attr_done) {
        cudaFuncSetAttribute(step_kernel, cudaFuncAttributeMaxDynamicSharedMemorySize, SM_DYN);
        attr_done = true;
    }

    void *p_h1, *p_h2, *p_th;
    cudaGetSymbolAddress(&p_h1, g_h1);
    cudaGetSymbolAddress(&p_h2, g_h2);
    cudaGetSymbolAddress(&p_th, g_theta);   // g_theta[0]

    size_t npk = (size_t)NT * NT * 32;
    cvt_E_pack<<<(unsigned)((npk + 255) / 256), 256>>>(A);

    mlp1_kernel<<<(H1n * 4 + 255) / 256, 256>>>(W1, b1, xs);
    matvec4<<<(H2n * 32 + 255) / 256, 256>>>(W2, b2, (const float*)p_h1, (float*)p_h2, H2n, H1n, 1);
    matvec4<<<((size_t)Ln * 32 + 255) / 256, 256>>>(W3, b3, (const float*)p_h2, (float*)p_th, Ln, H2n, 0);
    cvt_th0<<<(Ln * 4 + 255) / 256, 256>>>();

    for (int i = 0; i < Tt; i++)
        step_kernel<<<399, 256, SM_DYN>>>(i, xs, ts, Bm, out);

    root_final<<<1, 256>>>(ts, out);
}